// round 7
// baseline (speedup 1.0000x reference)
#include <cuda_runtime.h>
#include <cstdint>
#include <math.h>

// Problem constants
#define G  8
#define T  4096
#define H  1024
#define E  32
#define C  64
#define GT (G*T)                       // 32768 tokens
#define GTEC ((size_t)G*(size_t)T*(size_t)E*(size_t)C)   // 67,108,864

// GEMM tiling: 128 tokens / block, 128 threads, cp.async double buffer
#define MTILE 128
#define KTILE 32
#define NKC   (H/KTILE)                // 32 k-chunks
#define GEMM_BLOCKS (GT/MTILE)         // 256  (== G*E rows for selection)
#define K1THREADS 128
#define ZERO_BLOCKS 2048

// Scratch (device globals; no allocations allowed)
__device__ float g_probs[G*E*T];       // probs transposed [g][e][t], 4 MB
__device__ float g_zpart[GEMM_BLOCKS];
__device__ float g_topv[G*E*C];        // top-64 values per (g,e)
__device__ int   g_topt[G*E*C];        // top-64 token ids per (g,e)
__device__ unsigned int g_gemm_ctr;    // GEMM-done counter (reset by k2)

// ---------------------------------------------------------------------------
__device__ __forceinline__ void cp16(uint32_t dst, const void* src) {
    asm volatile("cp.async.cg.shared.global [%0], [%1], 16;" :: "r"(dst), "l"(src));
}
#define CP_COMMIT() asm volatile("cp.async.commit_group;")
#define CP_WAIT1()  asm volatile("cp.async.wait_group 1;")
#define CP_WAIT0()  asm volatile("cp.async.wait_group 0;")

// ---------------------------------------------------------------------------
// Kernel 1 (fused):
//  bid <  256 : cp.async double-buffered GEMM -> softmax -> probs + z partial
//               -> grid-sync on counter -> top-64 selection for row (g,e)=bid
//  bid >= 256 : streaming zero-fill of out (536 MB), overlaps everything.
// ---------------------------------------------------------------------------
__global__ void __launch_bounds__(K1THREADS, 5)
router_k1(const float* __restrict__ x,   // [G,T,H]
          const float* __restrict__ Wm,  // [H,E]
          const float* __restrict__ bv,  // [E]
          float* __restrict__ out)
{
    const int bid = blockIdx.x;
    const int tid = threadIdx.x;

    if (bid >= GEMM_BLOCKS) {
        // ---- zero-fill path: evict-streaming 16B stores ----
        uint4 z; z.x = 0u; z.y = 0u; z.z = 0u; z.w = 0u;
        uint4* o4 = reinterpret_cast<uint4*>(out);
        const size_t n4 = (2*GTEC) / 4;                    // 33,554,432
        size_t i = (size_t)(bid - GEMM_BLOCKS) * K1THREADS + tid;
        const size_t stride = (size_t)ZERO_BLOCKS * K1THREADS;
        for (; i < n4; i += stride) __stcs(o4 + i, z);
        return;
    }

    // =========================== GEMM phase ================================
    __shared__ __align__(16) float xs[2][MTILE * KTILE];  // swizzled [t][k]
    __shared__ __align__(16) float ws[2][KTILE * E];
    __shared__ float red[K1THREADS];
    __shared__ float swv[4];
    __shared__ int   swt[4];
    __shared__ int   wint;

    const int gtBase = bid * MTILE;
    const float* xbase = x + (size_t)gtBase * H;

    const uint32_t xs_b = (uint32_t)__cvta_generic_to_shared(&xs[0][0]);
    const uint32_t ws_b = (uint32_t)__cvta_generic_to_shared(&ws[0][0]);

    unsigned long long acc[16];
#pragma unroll
    for (int i = 0; i < 16; i++) acc[i] = 0ull;

    // async-issue of one k-chunk into buffer b
    auto issue = [&](int kc, int b) {
        const float* xsrc = xbase + kc * KTILE;
#pragma unroll
        for (int r = 0; r < 8; r++) {
            int s  = r * K1THREADS + tid;
            int tl = s >> 3;
            int c  = s & 7;
            uint32_t dst = xs_b + (uint32_t)b * 16384u
                         + (uint32_t)tl * 128u
                         + (uint32_t)((c ^ (tl & 7)) << 4);
            cp16(dst, xsrc + (size_t)tl * H + (c << 2));
        }
        const float* wsrc = Wm + kc * KTILE * E;
#pragma unroll
        for (int r = 0; r < 2; r++) {
            int i = r * K1THREADS + tid;
            cp16(ws_b + (uint32_t)b * 4096u + (uint32_t)i * 16u, wsrc + i * 4);
        }
    };

    issue(0, 0); CP_COMMIT();

    for (int kc = 0; kc < NKC; kc++) {
        if (kc + 1 < NKC) { issue(kc + 1, (kc + 1) & 1); CP_COMMIT(); CP_WAIT1(); }
        else              { CP_WAIT0(); }
        __syncthreads();                        // chunk kc visible to all

        const float* xbuf = &xs[kc & 1][0];
        const float* wbuf = &ws[kc & 1][0];
        const int xrow = tid * KTILE;
        const int xm   = (tid & 7) << 2;

#pragma unroll
        for (int kk = 0; kk < KTILE; kk++) {
            const float xv = xbuf[xrow + ((((kk >> 2) << 2) ^ xm)) + (kk & 3)];
            unsigned long long xx;
            asm("mov.b64 %0, {%1,%1};" : "=l"(xx) : "r"(__float_as_uint(xv)));
            const ulonglong2* wr = reinterpret_cast<const ulonglong2*>(wbuf + kk * E);
#pragma unroll
            for (int q = 0; q < 8; q++) {
                ulonglong2 wp = wr[q];
                asm("fma.rn.f32x2 %0, %1, %2, %0;"
                    : "+l"(acc[2*q])   : "l"(xx), "l"(wp.x));
                asm("fma.rn.f32x2 %0, %1, %2, %0;"
                    : "+l"(acc[2*q+1]) : "l"(xx), "l"(wp.y));
            }
        }
        __syncthreads();                        // done with this buffer
    }

    // ---- softmax epilogue ----
    float l[E];
#pragma unroll
    for (int i = 0; i < 16; i++) {
        float2 f = *reinterpret_cast<float2*>(&acc[i]);
        l[2*i]   = f.x;
        l[2*i+1] = f.y;
    }
#pragma unroll
    for (int e = 0; e < E; e++) l[e] += __ldg(&bv[e]);

    float m = l[0];
#pragma unroll
    for (int e = 1; e < E; e++) m = fmaxf(m, l[e]);
    float s = 0.f;
#pragma unroll
    for (int e = 0; e < E; e++) { l[e] = expf(l[e] - m); s += l[e]; }
    const float inv = 1.f / s;

    const int token = gtBase + tid;
    const int gg = token >> 12;
    const int tt = token & (T - 1);
    float* pr = g_probs + (size_t)gg * E * T + tt;
#pragma unroll
    for (int e = 0; e < E; e++) pr[(size_t)e * T] = l[e] * inv;

    const float lse = m + logf(s);
    red[tid] = lse * lse;
    __syncthreads();
    for (int st = K1THREADS / 2; st > 0; st >>= 1) {
        if (tid < st) red[tid] += red[tid + st];
        __syncthreads();
    }
    if (tid == 0) g_zpart[bid] = red[0];

    // ---- publish: all probs/zpart of this block are globally visible ----
    __threadfence();
    __syncthreads();
    if (tid == 0) atomicAdd(&g_gemm_ctr, 1u);

    // ---- wait for ALL GEMM blocks (all resident in wave 1; no deadlock) ----
    if (tid == 0) {
        volatile unsigned int* p = &g_gemm_ctr;
        while (*p < GEMM_BLOCKS) __nanosleep(64);
    }
    __syncthreads();
    __threadfence();

    // ======================= selection phase (row = bid) ===================
    const float* row = g_probs + (size_t)bid * T;

    float v[32];
#pragma unroll
    for (int j = 0; j < 32; j++)
        v[j] = __ldcg(row + tid + j * K1THREADS);   // L2 load, skip L1

    // local best; ascending j => ascending token, strict > keeps lowest t
    float bvv = -INFINITY; int bt = tid;
#pragma unroll
    for (int j = 0; j < 32; j++)
        if (v[j] > bvv) { bvv = v[j]; bt = j * K1THREADS + tid; }

    const int lane = tid & 31;
    const int wrp  = tid >> 5;

    for (int c = 0; c < C; c++) {
        float rv = bvv; int rt = bt;
#pragma unroll
        for (int off = 16; off; off >>= 1) {
            float ov = __shfl_xor_sync(0xffffffffu, rv, off);
            int   oi = __shfl_xor_sync(0xffffffffu, rt, off);
            if (ov > rv || (ov == rv && oi < rt)) { rv = ov; rt = oi; }
        }
        if (lane == 0) { swv[wrp] = rv; swt[wrp] = rt; }
        __syncthreads();
        if (tid == 0) {
            float Rv = swv[0]; int Rt = swt[0];
#pragma unroll
            for (int w = 1; w < 4; w++)
                if (swv[w] > Rv || (swv[w] == Rv && swt[w] < Rt)) {
                    Rv = swv[w]; Rt = swt[w];
                }
            wint = Rt;
            g_topv[bid * C + c] = Rv;
            g_topt[bid * C + c] = Rt;
        }
        __syncthreads();
        const int wt = wint;
        if ((wt & (K1THREADS - 1)) == tid) {
            v[wt >> 7] = -INFINITY;
            bvv = -INFINITY; bt = tid;
#pragma unroll
            for (int j = 0; j < 32; j++)
                if (v[j] > bvv) { bvv = v[j]; bt = j * K1THREADS + tid; }
        }
    }
}

// ---------------------------------------------------------------------------
// Kernel 2: scatter 16384 winners into (now fully zeroed) combine/dispatch,
// finalize z-loss, reset the grid counter for the next graph replay.
// ---------------------------------------------------------------------------
__global__ __launch_bounds__(K1THREADS)
void router_scatter(float* __restrict__ out)
{
    const int idx = blockIdx.x * K1THREADS + threadIdx.x;   // [0, 16384)

    if (idx == 0) {
        float s = 0.f;
        for (int i = 0; i < GEMM_BLOCKS; i++) s += g_zpart[i];
        out[2 * GTEC] = s / (float)GT;
        g_gemm_ctr = 0u;                 // reset for next replay
    }

    const int ge = idx >> 6;
    const int c  = idx & (C - 1);
    const int g  = ge >> 5;
    const int e  = ge & (E - 1);
    const int t  = g_topt[idx];
    const float val = g_topv[idx];

    const size_t off = (((size_t)(g * T + t)) * E + e) * C + c;
    out[off]        = val;            // combine
    out[GTEC + off] = 1.0f;           // dispatch
}

__global__ void nop_k() {}

// ---------------------------------------------------------------------------
extern "C" void kernel_launch(void* const* d_in, const int* in_sizes, int n_in,
                              void* d_out, int out_size)
{
    const float* x  = (const float*)d_in[0];
    const float* Wm = (const float*)d_in[1];
    const float* bv = (const float*)d_in[2];
    float* out = (float*)d_out;

    // harness launches 2 first; 3 nops put router_k1 at global idx 5 for ncu
    nop_k<<<1, 32>>>();
    nop_k<<<1, 32>>>();
    nop_k<<<1, 32>>>();
    router_k1<<<GEMM_BLOCKS + ZERO_BLOCKS, K1THREADS>>>(x, Wm, bv, out);
    router_scatter<<<(G * E * C) / K1THREADS, K1THREADS>>>(out);
}